// round 8
// baseline (speedup 1.0000x reference)
#include <cuda_runtime.h>
#include <cstdint>

// GCN 2-layer, DENSE formulation:
//   out = dinv ⊙ [ (Â + I) @ (dinv ⊙ (X @ W)) ] + b
// Â densified to fp32 counts (exact), GEMM vs dense Â done with tf32 mma.sync.
// N=10000, d=128, E=640000, edges int32.
// Launches (slot 4 = profiled):
//   1 k_prep      blocks [0,PB): smem dst-histogram ; rest: zero A (405MB)
//   2 k_scanbins  deg -> dinv = rsqrt(deg+1)
//   3 k_fillgemm  blocks [0,nGemm): Hs1 = dinv⊙(X@W1) ; rest: A[dst][src]+=1, A[i][i]+=1
//   4 k_dense     x1 = dinv⊙(A@Hs1)+b1          <-- profiled
//   5 k_gemmhs    Hs2 = dinv⊙(x1@W2)
//   6 k_dense     out = dinv⊙(A@Hs2)+b2

#define DF    128
#define MAXN  10048
#define NROWS 10112          // 79 * 128  (A row pad)
#define KPAD  10016          // 313 * 32  (A col / Hs row pad)
#define PB    64             // histogram blocks
#define ZB    2048           // zeroing blocks

__device__ float g_A   [(size_t)NROWS * KPAD];   // dense Â+I (fp32 counts)
__device__ int   g_hist[PB * MAXN];
__device__ float g_dinv[MAXN];
__device__ float g_Hs  [(size_t)KPAD * DF];      // dinv ⊙ (X@W), rows >= n stay 0
__device__ float g_x1  [(size_t)KPAD * DF];      // layer-1 output

// ---------------------------------------------------------------------------
__device__ __forceinline__ uint32_t f2tf(float f) {
    uint32_t u;
    asm("cvt.rna.tf32.f32 %0, %1;" : "=r"(u) : "f"(f));
    return u;
}

__device__ __forceinline__ void mma8(float* c, const uint32_t* a,
                                     uint32_t b0, uint32_t b1) {
    asm volatile(
        "mma.sync.aligned.m16n8k8.row.col.f32.tf32.tf32.f32 "
        "{%0,%1,%2,%3},{%4,%5,%6,%7},{%8,%9},{%0,%1,%2,%3};"
        : "+f"(c[0]), "+f"(c[1]), "+f"(c[2]), "+f"(c[3])
        : "r"(a[0]), "r"(a[1]), "r"(a[2]), "r"(a[3]), "r"(b0), "r"(b1));
}

// ---------------------------------------------------------------------------
// 1: fused histogram (blocks [0,PB)) + zero A (blocks [PB,PB+ZB))
__global__ void __launch_bounds__(256) k_prep(const int* __restrict__ edges,
                                              int E, int n, int chunk) {
    __shared__ int hist[MAXN];
    int tid = threadIdx.x;
    if (blockIdx.x < PB) {
        for (int i = tid; i < n; i += 256) hist[i] = 0;
        __syncthreads();
        int b   = blockIdx.x;
        int beg = b * chunk;
        int end = min(beg + chunk, E);
        for (int e = beg + tid; e < end; e += 256)
            atomicAdd(&hist[edges[E + e]], 1);
        __syncthreads();
        for (int i = tid; i < n; i += 256)
            g_hist[b * MAXN + i] = hist[i];
    } else {
        size_t total = (size_t)NROWS * KPAD / 4;
        float4* A4 = (float4*)g_A;
        float4 z = make_float4(0.f, 0.f, 0.f, 0.f);
        for (size_t i = (size_t)(blockIdx.x - PB) * 256 + tid; i < total;
             i += (size_t)ZB * 256)
            A4[i] = z;
    }
}

// 2: deg -> dinv
__global__ void __launch_bounds__(256) k_scanbins(int n) {
    int bin = blockIdx.x * blockDim.x + threadIdx.x;
    if (bin >= n) return;
    int run = 0;
#pragma unroll 8
    for (int p = 0; p < PB; p++) run += g_hist[p * MAXN + bin];
    g_dinv[bin] = rsqrtf((float)(run + 1));   // +1 self loop
}

// ---------------------------------------------------------------------------
// GEMM body: Hs[n,128] = dinv ⊙ (X[n,128] @ W[128,128]); 32 rows/block.
__device__ __forceinline__ void gemmhs_body(const float4* __restrict__ X4,
                                            const float* __restrict__ W,
                                            float4* __restrict__ Y4,
                                            int n, int bid) {
    __shared__ float4 xs4[32 * 32];
    const float4* W4 = (const float4*)W;

    int tid  = threadIdx.x;
    int row0 = bid * 32;

#pragma unroll
    for (int j = 0; j < 4; j++) {
        int idx = tid + 256 * j;
        int gr  = row0 + (idx >> 5);
        xs4[idx] = (gr < n) ? X4[gr * 32 + (idx & 31)]
                            : make_float4(0.f, 0.f, 0.f, 0.f);
    }
    __syncthreads();

    int c4 = tid & 31;
    int rg = tid >> 5;

    float4 acc[4];
#pragma unroll
    for (int i = 0; i < 4; i++) acc[i] = make_float4(0.f, 0.f, 0.f, 0.f);

#pragma unroll 4
    for (int k0 = 0; k0 < 128; k0 += 4) {
        float4 w0 = __ldg(&W4[(k0 + 0) * 32 + c4]);
        float4 w1 = __ldg(&W4[(k0 + 1) * 32 + c4]);
        float4 w2 = __ldg(&W4[(k0 + 2) * 32 + c4]);
        float4 w3 = __ldg(&W4[(k0 + 3) * 32 + c4]);
#pragma unroll
        for (int i = 0; i < 4; i++) {
            float4 a = xs4[(rg + 8 * i) * 32 + (k0 >> 2)];
            acc[i].x += a.x * w0.x + a.y * w1.x + a.z * w2.x + a.w * w3.x;
            acc[i].y += a.x * w0.y + a.y * w1.y + a.z * w2.y + a.w * w3.y;
            acc[i].z += a.x * w0.z + a.y * w1.z + a.z * w2.z + a.w * w3.z;
            acc[i].w += a.x * w0.w + a.y * w1.w + a.z * w2.w + a.w * w3.w;
        }
    }

#pragma unroll
    for (int i = 0; i < 4; i++) {
        int gr = row0 + rg + 8 * i;
        if (gr < n) {
            float dv = g_dinv[gr];
            float4 o = acc[i];
            o.x *= dv; o.y *= dv; o.z *= dv; o.w *= dv;
            Y4[gr * 32 + c4] = o;
        }
    }
}

__global__ void __launch_bounds__(256) k_gemmhs(const float4* __restrict__ X4,
                                                const float* __restrict__ W,
                                                float4* __restrict__ Y4, int n) {
    gemmhs_body(X4, W, Y4, n, blockIdx.x);
}

// 3: fused layer-1 gemm+scale (blocks [0,nGemm)) + A fill (rest; spread atomics)
__global__ void __launch_bounds__(256) k_fillgemm(const float4* __restrict__ X4,
                                                  const float* __restrict__ W,
                                                  float4* __restrict__ Y4, int n,
                                                  const int* __restrict__ edges,
                                                  int E, int nGemm) {
    if (blockIdx.x >= nGemm) {
        int idx = (blockIdx.x - nGemm) * 256 + threadIdx.x;
        if (idx < E + n) {
            int r, c;
            if (idx < E) { c = edges[idx]; r = edges[E + idx]; }  // A[dst][src]
            else         { r = c = idx - E; }                      // +I diagonal
            atomicAdd(&g_A[(size_t)r * KPAD + c], 1.0f);
        }
        return;
    }
    gemmhs_body(X4, W, Y4, n, blockIdx.x);
}

// ---------------------------------------------------------------------------
// 4/6: OUT[m0:m0+128, nb0:nb0+64] = dinv ⊙ (A @ Hs) + b   via tf32 mma.sync
// grid (79, 2), 256 threads; warp tile 32x32 (4 row-warps x 2 col-warps).
__global__ void __launch_bounds__(256) k_dense(const float* __restrict__ Hs,
                                               const float* __restrict__ bias,
                                               float* __restrict__ out, int n) {
    __shared__ uint32_t As[128 * 36];   // 128 rows x 32 k (stride 36, tf32 bits)
    __shared__ uint32_t Bs[32 * 72];    // 32 k x 64 n    (stride 72, tf32 bits)

    int tid  = threadIdx.x;
    int m0   = blockIdx.x * 128;
    int nb0  = blockIdx.y * 64;
    int wid  = tid >> 5;
    int lane = tid & 31;
    int g    = lane >> 2;     // group id
    int t    = lane & 3;      // thread-in-group
    int wr0  = (wid >> 1) * 32;
    int wc0  = (wid & 1) * 32;

    const float4* A4 = (const float4*)g_A;
    const float4* H4 = (const float4*)Hs;

    float c[2][4][4];
#pragma unroll
    for (int mi = 0; mi < 2; mi++)
#pragma unroll
        for (int j = 0; j < 4; j++)
#pragma unroll
            for (int q = 0; q < 4; q++) c[mi][j][q] = 0.f;

    float4 pa[4], pb[2];

    // prefetch stage k0=0
#pragma unroll
    for (int p = 0; p < 4; p++) {
        int idx = tid + 256 * p;
        pa[p] = A4[(size_t)(m0 + (idx >> 3)) * (KPAD / 4) + (idx & 7)];
    }
#pragma unroll
    for (int p = 0; p < 2; p++) {
        int idx = tid + 256 * p;
        pb[p] = H4[(size_t)(idx >> 4) * 32 + (nb0 >> 2) + (idx & 15)];
    }

    for (int k0 = 0; k0 < KPAD; k0 += 32) {
        __syncthreads();
        // store prefetched stage (fp32 -> tf32 bits)
#pragma unroll
        for (int p = 0; p < 4; p++) {
            int idx = tid + 256 * p;
            uint32_t* d = &As[(idx >> 3) * 36 + (idx & 7) * 4];
            d[0] = f2tf(pa[p].x); d[1] = f2tf(pa[p].y);
            d[2] = f2tf(pa[p].z); d[3] = f2tf(pa[p].w);
        }
#pragma unroll
        for (int p = 0; p < 2; p++) {
            int idx = tid + 256 * p;
            uint32_t* d = &Bs[(idx >> 4) * 72 + (idx & 15) * 4];
            d[0] = f2tf(pb[p].x); d[1] = f2tf(pb[p].y);
            d[2] = f2tf(pb[p].z); d[3] = f2tf(pb[p].w);
        }
        __syncthreads();

        int kn = k0 + 32;
        if (kn < KPAD) {     // prefetch next stage while computing
#pragma unroll
            for (int p = 0; p < 4; p++) {
                int idx = tid + 256 * p;
                pa[p] = A4[(size_t)(m0 + (idx >> 3)) * (KPAD / 4) + (kn >> 2) + (idx & 7)];
            }
#pragma unroll
            for (int p = 0; p < 2; p++) {
                int idx = tid + 256 * p;
                pb[p] = H4[(size_t)(kn + (idx >> 4)) * 32 + (nb0 >> 2) + (idx & 15)];
            }
        }

#pragma unroll
        for (int kk = 0; kk < 32; kk += 8) {
            uint32_t a[2][4];
#pragma unroll
            for (int mi = 0; mi < 2; mi++) {
                int row = wr0 + mi * 16 + g;
                a[mi][0] = As[row * 36 + kk + t];
                a[mi][1] = As[(row + 8) * 36 + kk + t];
                a[mi][2] = As[row * 36 + kk + t + 4];
                a[mi][3] = As[(row + 8) * 36 + kk + t + 4];
            }
#pragma unroll
            for (int j = 0; j < 4; j++) {
                int nn = wc0 + j * 8 + g;
                uint32_t b0 = Bs[(kk + t) * 72 + nn];
                uint32_t b1 = Bs[(kk + t + 4) * 72 + nn];
                mma8(c[0][j], a[0], b0, b1);
                mma8(c[1][j], a[1], b0, b1);
            }
        }
    }

    // epilogue: out = dinv[row]*acc + b[col]
#pragma unroll
    for (int mi = 0; mi < 2; mi++) {
#pragma unroll
        for (int j = 0; j < 4; j++) {
            int col = nb0 + wc0 + j * 8 + 2 * t;
            float bx = bias[col], by = bias[col + 1];
            int r0 = m0 + wr0 + mi * 16 + g;
            if (r0 < n) {
                float dv = g_dinv[r0];
                float2 v = make_float2(c[mi][j][0] * dv + bx,
                                       c[mi][j][1] * dv + by);
                *(float2*)&out[(size_t)r0 * DF + col] = v;
            }
            int r1 = r0 + 8;
            if (r1 < n) {
                float dv = g_dinv[r1];
                float2 v = make_float2(c[mi][j][2] * dv + bx,
                                       c[mi][j][3] * dv + by);
                *(float2*)&out[(size_t)r1 * DF + col] = v;
            }
        }
    }
}

// ---------------------------------------------------------------------------
extern "C" void kernel_launch(void* const* d_in, const int* in_sizes, int n_in,
                              void* d_out, int out_size) {
    const float* x     = (const float*)d_in[0];
    const int*   edges = (const int*)d_in[1];      // int32 (JAX x64 off)
    const float* W1    = (const float*)d_in[2];
    const float* b1    = (const float*)d_in[3];
    const float* W2    = (const float*)d_in[4];
    const float* b2    = (const float*)d_in[5];
    float*       out   = (float*)d_out;

    int N = in_sizes[0] / DF;     // 10000
    int E = in_sizes[1] / 2;      // 640000

    const int T = 256;
    int chunk = (E + PB - 1) / PB;
    int gBins = (N + T - 1) / T;
    int nGemm = (N + 31) / 32;
    int gFill = (E + N + T - 1) / T;
    dim3 gDense((N + 127) / 128, 2);

    // 1: histogram + zero A
    k_prep<<<PB + ZB, T>>>(edges, E, N, chunk);
    // 2: dinv
    k_scanbins<<<gBins, T>>>(N);
    // 3: Hs1 = dinv*(X@W1)  fused with A fill
    k_fillgemm<<<nGemm + gFill, T>>>((const float4*)x, W1, (float4*)g_Hs, N,
                                     edges, E, nGemm);
    // 4: x1 = dinv*(A@Hs1) + b1          (profiled slot)
    k_dense<<<gDense, T>>>(g_Hs, b1, g_x1, N);
    // 5: Hs2 = dinv*(x1@W2)
    k_gemmhs<<<nGemm, T>>>((const float4*)g_x1, W2, (float4*)g_Hs, N);
    // 6: out = dinv*(A@Hs2) + b2
    k_dense<<<gDense, T>>>(g_Hs, b2, out, N);
}